// round 11
// baseline (speedup 1.0000x reference)
#include <cuda_runtime.h>
#include <cuda_bf16.h>
#include <math.h>

#define NN   4096
#define FF   512
#define HH   60
#define CC   4
#define CAP  64      // max nnz per row of sub_adj (mean ~8.2)

// scratch (device globals; referenced ONLY from device code — see R3 post-mortem)
__device__ float g_deg[NN];          // zero at load; reset by k_xw prologue each run
__device__ float g_self[NN];         // 1/(deg_i+1) self-loop weight
__device__ int   g_cnt[NN];
__device__ int   g_cols[NN * CAP];
__device__ float g_vals[NN * CAP];   // after k_norm: fully normalized edge weight
__device__ float g_Ta[NN * HH];
__device__ float g_Tb[NN * HH];

__device__ __forceinline__ void cp16(unsigned s, const void* g) {
    asm volatile("cp.async.cg.shared.global [%0], [%1], 16;\n" :: "r"(s), "l"(g));
}

// ---------------------------------------------------------------------------
// K1: scan sub_adj (67 MB, HBM floor ~8.5 us), warp-ballot edge compaction,
// gather P_vec at nonzeros, sigmoid, column-degree atomic accumulation.
__global__ void k_build(const float* __restrict__ adj, const float* __restrict__ pvec) {
    int warp = (blockIdx.x * blockDim.x + threadIdx.x) >> 5;
    int lane = threadIdx.x & 31;
    if (warp >= NN) return;
    const int row = warp;
    const float4* rp = reinterpret_cast<const float4*>(adj + (size_t)row * NN);
    int cnt = 0;
    #pragma unroll 4
    for (int it = 0; it < NN / 128; ++it) {
        float4 v = rp[it * 32 + lane];
        int jb = it * 128 + lane * 4;
        float vv[4] = {v.x, v.y, v.z, v.w};
        #pragma unroll
        for (int q = 0; q < 4; ++q) {
            bool nz = (vv[q] != 0.0f);
            unsigned m = __ballot_sync(0xffffffffu, nz);
            if (nz) {
                int j = jb + q;
                int slot = cnt + __popc(m & ((1u << lane) - 1u));
                int a = row > j ? row : j;
                int b = row > j ? j : row;
                float p = pvec[(size_t)a * (a + 1) / 2 + b];   // tril idx a(a+1)/2+b
                float s = vv[q] / (1.0f + expf(-p));            // sigmoid(p)*adj
                if (slot < CAP) {
                    g_cols[row * CAP + slot] = j;
                    g_vals[row * CAP + slot] = s;
                }
                atomicAdd(&g_deg[j], s);
            }
            cnt += __popc(m);
        }
    }
    if (lane == 0) g_cnt[row] = cnt < CAP ? cnt : CAP;
}

// ---------------------------------------------------------------------------
// K2: fold D^{-1/2} into edges (reads g_deg directly; g_deg NOT reset here),
// g_self = 1/(deg_i+1), zero g_Ta for k_xw's atomic split-K accumulation.
__global__ void k_norm() {
    int gid = blockIdx.x * 256 + threadIdx.x;           // 65536 threads
    int row = gid >> 4, le = gid & 15;
    float di = rsqrtf(g_deg[row] + 1.0f);
    int cnt = g_cnt[row];
    for (int e = le; e < cnt; e += 16) {
        int j = g_cols[row * CAP + e];
        g_vals[row * CAP + e] *= di * rsqrtf(g_deg[j] + 1.0f);
    }
    if (le == 0) g_self[row] = di * di;
    for (int i = gid; i < NN * HH; i += 65536) g_Ta[i] = 0.0f;
}

// ---------------------------------------------------------------------------
// K3: g_Ta += x @ W1, SPLIT-K x2: block bx handles rows [bx>>1 * 32, +32),
// K-half (bx&1)*256. Exactly 2 atomic contributions per element ->
// bitwise deterministic. Prologue resets g_deg for graph replay.
__global__ void __launch_bounds__(256) k_xw(const float* __restrict__ x,
                                            const float* __restrict__ W) {
    int gid = blockIdx.x * 256 + threadIdx.x;
    if (gid < NN) g_deg[gid] = 0.0f;

    __shared__ __align__(16) float As[2][32][36];
    __shared__ __align__(16) float Ws[2][32][64];

    const int t  = threadIdx.x;
    const int tx = t & 15;
    const int ty = t >> 4;
    const int r0 = (blockIdx.x >> 1) * 32;
    const int kb = (blockIdx.x & 1) * 256;

    { int b = t >> 7, rr = (t >> 2) & 31, cc = 60 + (t & 3); Ws[b][rr][cc] = 0.0f; }

    const int arow = t >> 3;
    const int akk  = (t & 7) * 4;
    const int wk   = t >> 3;
    const int wc   = (t & 7) * 8;

    auto issue = [&](int tile, int buf) {
        int k0 = kb + tile * 32;
        unsigned sA = (unsigned)__cvta_generic_to_shared(&As[buf][arow][akk]);
        cp16(sA, x + (size_t)(r0 + arow) * FF + k0 + akk);
        unsigned sW = (unsigned)__cvta_generic_to_shared(&Ws[buf][wk][wc]);
        cp16(sW, W + (size_t)(k0 + wk) * HH + wc);
        if (wc + 4 < HH)
            cp16(sW + 16, W + (size_t)(k0 + wk) * HH + wc + 4);
        asm volatile("cp.async.commit_group;\n");
    };

    unsigned long long acc[2][2] = {{0ull, 0ull}, {0ull, 0ull}};

    issue(0, 0);
    int buf = 0;
    for (int tile = 0; tile < 8; ++tile) {
        __syncthreads();
        if (tile < 7) {
            issue(tile + 1, buf ^ 1);
            asm volatile("cp.async.wait_group 1;\n");
        } else {
            asm volatile("cp.async.wait_group 0;\n");
        }
        __syncthreads();
        #pragma unroll
        for (int k = 0; k < 32; ++k) {
            unsigned a0 = __float_as_uint(As[buf][2 * ty + 0][k]);
            unsigned a1 = __float_as_uint(As[buf][2 * ty + 1][k]);
            unsigned long long pa0, pa1;
            asm("mov.b64 %0, {%1, %1};" : "=l"(pa0) : "r"(a0));
            asm("mov.b64 %0, {%1, %1};" : "=l"(pa1) : "r"(a1));
            ulonglong2 w = *reinterpret_cast<const ulonglong2*>(&Ws[buf][k][4 * tx]);
            asm("fma.rn.f32x2 %0, %1, %2, %0;" : "+l"(acc[0][0]) : "l"(pa0), "l"(w.x));
            asm("fma.rn.f32x2 %0, %1, %2, %0;" : "+l"(acc[0][1]) : "l"(pa0), "l"(w.y));
            asm("fma.rn.f32x2 %0, %1, %2, %0;" : "+l"(acc[1][0]) : "l"(pa1), "l"(w.x));
            asm("fma.rn.f32x2 %0, %1, %2, %0;" : "+l"(acc[1][1]) : "l"(pa1), "l"(w.y));
        }
        buf ^= 1;
    }

    if (4 * tx < HH) {
        #pragma unroll
        for (int i = 0; i < 2; ++i) {
            unsigned lo0, hi0, lo1, hi1;
            asm("mov.b64 {%0, %1}, %2;" : "=r"(lo0), "=r"(hi0) : "l"(acc[i][0]));
            asm("mov.b64 {%0, %1}, %2;" : "=r"(lo1), "=r"(hi1) : "l"(acc[i][1]));
            float* d = &g_Ta[(size_t)(r0 + 2 * ty + i) * HH + 4 * tx];
            atomicAdd(d + 0, __uint_as_float(lo0));
            atomicAdd(d + 1, __uint_as_float(hi0));
            atomicAdd(d + 2, __uint_as_float(lo1));
            atomicAdd(d + 3, __uint_as_float(hi1));
        }
    }
}

// ---------------------------------------------------------------------------
// K4: fused layer, 512 thr = 8 groups x 64 lanes, 1 col/lane, 8 rows/block.
// Ws staged via cp.async OVERLAPPED with the SpMM gather.
// FIX(R9): chunk coverage was 0..449 + 512..899, leaving 450..511 garbage.
// Now 0..511 (all threads) + 512..899.
__global__ void __launch_bounds__(512) k_layer(int src, const float* __restrict__ bias,
                                               const float* __restrict__ Wnext) {
    const float* __restrict__ Tin = src ? g_Tb : g_Ta;
    float* __restrict__ Tout      = src ? g_Ta : g_Tb;
    __shared__ __align__(16) float Ws[HH * HH];   // 3600 floats = 900 x 16B chunks
    __shared__ float hs[8][HH];
    int t = threadIdx.x, c = t & 63, g = t >> 6;
    int row = blockIdx.x * 8 + g;

    // stage Ws asynchronously (needed only in dense phase)
    {
        unsigned base = (unsigned)__cvta_generic_to_shared(Ws);
        cp16(base + t * 16, Wnext + t * 4);                    // chunks 0..511
        int u = t + 512;
        if (u < 900) cp16(base + u * 16, Wnext + u * 4);       // chunks 512..899
        asm volatile("cp.async.commit_group;\n");
    }

    if (c < HH) {
        const int*   cp = &g_cols[row * CAP];
        const float* vp = &g_vals[row * CAP];
        int cnt = g_cnt[row];
        float a0 = g_self[row] * Tin[row * HH + c];
        float a1 = 0.f, a2 = 0.f, a3 = 0.f;
        int e = 0;
        for (; e + 4 <= cnt; e += 4) {
            int4   cc = *reinterpret_cast<const int4*>(&cp[e]);
            float4 ww = *reinterpret_cast<const float4*>(&vp[e]);
            a0 += ww.x * Tin[cc.x * HH + c];
            a1 += ww.y * Tin[cc.y * HH + c];
            a2 += ww.z * Tin[cc.z * HH + c];
            a3 += ww.w * Tin[cc.w * HH + c];
        }
        for (; e < cnt; ++e) a0 += vp[e] * Tin[cp[e] * HH + c];
        hs[g][c] = fmaxf((a0 + a1) + (a2 + a3) + bias[c], 0.0f);
    }
    asm volatile("cp.async.wait_group 0;\n");
    __syncthreads();
    if (c < HH) {
        float o0 = 0.f, o1 = 0.f, o2 = 0.f, o3 = 0.f;
        #pragma unroll
        for (int k = 0; k < HH; k += 4) {
            o0 += hs[g][k + 0] * Ws[(k + 0) * HH + c];
            o1 += hs[g][k + 1] * Ws[(k + 1) * HH + c];
            o2 += hs[g][k + 2] * Ws[(k + 2) * HH + c];
            o3 += hs[g][k + 3] * Ws[(k + 3) * HH + c];
        }
        Tout[row * HH + c] = (o0 + o1) + (o2 + o3);
    }
}

// ---------------------------------------------------------------------------
// K5: final: H3 = SpMM(g_Ta)+b3; logits = H3 @ lin_w + lin_b; log_softmax.
__global__ void __launch_bounds__(512) k_final(const float* __restrict__ b3,
                                               const float* __restrict__ lw,
                                               const float* __restrict__ lb,
                                               float* __restrict__ out) {
    const float* __restrict__ Tin = g_Ta;
    __shared__ float lws[HH * CC];
    __shared__ float hs[8][HH];
    __shared__ float lg[8][CC];
    int t = threadIdx.x, c = t & 63, g = t >> 6;
    int row = blockIdx.x * 8 + g;
    if (t < HH * CC) lws[t] = lw[t];

    if (c < HH) {
        const int*   cp = &g_cols[row * CAP];
        const float* vp = &g_vals[row * CAP];
        int cnt = g_cnt[row];
        float a0 = g_self[row] * Tin[row * HH + c];
        float a1 = 0.f, a2 = 0.f, a3 = 0.f;
        int e = 0;
        for (; e + 4 <= cnt; e += 4) {
            int4   cc = *reinterpret_cast<const int4*>(&cp[e]);
            float4 ww = *reinterpret_cast<const float4*>(&vp[e]);
            a0 += ww.x * Tin[cc.x * HH + c];
            a1 += ww.y * Tin[cc.y * HH + c];
            a2 += ww.z * Tin[cc.z * HH + c];
            a3 += ww.w * Tin[cc.w * HH + c];
        }
        for (; e < cnt; ++e) a0 += vp[e] * Tin[cp[e] * HH + c];
        hs[g][c] = (a0 + a1) + (a2 + a3) + b3[c];
    }
    __syncthreads();
    if (c < CC) {
        float o = lb[c];
        #pragma unroll
        for (int k = 0; k < HH; ++k)
            o += hs[g][k] * lws[k * CC + c];
        lg[g][c] = o;
    }
    __syncthreads();
    if (c < CC) {
        float m = fmaxf(fmaxf(lg[g][0], lg[g][1]), fmaxf(lg[g][2], lg[g][3]));
        float s = expf(lg[g][0] - m) + expf(lg[g][1] - m) +
                  expf(lg[g][2] - m) + expf(lg[g][3] - m);
        out[(size_t)row * CC + c] = lg[g][c] - m - logf(s);
    }
}

// ---------------------------------------------------------------------------
// Inputs resolved BY ELEMENT COUNT; same-size ties by relative order.
extern "C" void kernel_launch(void* const* d_in, const int* in_sizes, int n_in,
                              void* d_out, int out_size) {
    const float *x = 0, *adj = 0, *pvec = 0, *W1 = 0, *b1 = 0, *W2 = 0, *b2 = 0,
                *W3 = 0, *b3 = 0, *lin_w = 0, *lin_b = 0;
    int nb = 0, nw = 0;
    for (int i = 0; i < n_in; ++i) {
        const float* p = (const float*)d_in[i];
        switch (in_sizes[i]) {
            case NN * FF:            x = p;    break;
            case NN * NN:            adj = p;  break;
            case (NN * (NN + 1)) / 2: pvec = p; break;
            case FF * HH:            W1 = p;   break;
            case HH * HH:
                if (nw == 0) W2 = p; else W3 = p;
                ++nw; break;
            case HH:
                if (nb == 0) b1 = p; else if (nb == 1) b2 = p; else b3 = p;
                ++nb; break;
            case HH * CC:            lin_w = p; break;
            case CC:                 lin_b = p; break;
            default: break;
        }
    }
    float* out = (float*)d_out;

    k_build<<<NN / 8, 256>>>(adj, pvec);       // 1 warp/row; accumulates g_deg
    k_norm<<<256, 256>>>();                    // fold D^{-1/2}, g_self, zero g_Ta
    k_xw<<<256, 256>>>(x, W1);                 // g_Ta += x@W1 (split-K x2, atomic)
    k_layer<<<NN / 8, 512>>>(0, b1, W2);       // g_Ta -> g_Tb
    k_layer<<<NN / 8, 512>>>(1, b2, W3);       // g_Tb -> g_Ta
    k_final<<<NN / 8, 512>>>(b3, lin_w, lin_b, out);
}